// round 16
// baseline (speedup 1.0000x reference)
#include <cuda_runtime.h>
#include <math.h>

// ---------------------------------------------------------------------------
// Shapes: N=16, F=5, V=4 -> 320 images of 3x224x224
// conv1: 3->3, 3x3, s2: 224->111 ; maxpool3/3 -> 37 ; relu
// conv2: 3->1, 3x3, s2: 37->18   ; maxpool3/3 -> 6  ; relu
// flatten 36 -> linear -> feat[320,6]; graph ops + MLP -> [16,6]
//
// R16: K1 = conv1 grid with LAST-ARRIVER conv2 fused in (R11-proven conv-
// speed-neutral: the block that completes an image's 1369 conv1 outputs
// immediately runs that image's conv2+pool+linear -> g_feat, overlapped with
// other blocks' conv1). No spins anywhere. K2 = pure 16-block readout
// (stream order provides g_feat visibility). This deletes the 320-block
// tiny-work epilogue grid AND all parked spinners — the ghost's last
// suspects — and makes K2's standalone cost directly measurable.
// ---------------------------------------------------------------------------

#define NIMG 320
#define H1S (3 * 1369)
#define TOTAL1 (NIMG * 1369)
#define NBLK1 1712

__device__ float g_h1[NIMG * H1S];
__device__ float g_feat[NIMG * 6];
__device__ int g_imgcnt[NIMG];       // zero-init; reset by K2 each replay

// ---------------- Kernel 1: conv1 + pool + relu, last-arriver conv2 --------
__global__ __launch_bounds__(256, 3)
void conv_fused_kernel(const float* __restrict__ nodes,
                       const float* __restrict__ c1w, const float* __restrict__ c1b,
                       const float* __restrict__ c2w, const float* __restrict__ c2b,
                       const float* __restrict__ lw,  const float* __restrict__ lb)
{
    __shared__ float sw[81];
    __shared__ float sb[3];
    __shared__ float sw2[27];
    __shared__ float s_conv[36][9];
    __shared__ float s_hs[36];
    __shared__ int   s_img[2];
    __shared__ int   s_do;

    const int t = threadIdx.x;
    if (t < 81) sw[t] = c1w[t];
    if (t < 3)  sb[t] = c1b[t];
    if (t >= 128 && t < 155) sw2[t - 128] = c2w[t - 128];
    __syncthreads();

    const int lo  = blockIdx.x * 256;
    const int idx = lo + t;

    if (idx < TOTAL1) {
        int px  = idx % 37;
        int rem = idx / 37;
        int py  = rem % 37;
        int img = rem / 37;

        const float* base = nodes + (size_t)img * 150528
                                  + (size_t)(6 * py) * 224 + 6 * px;
        float acc[9][3];
#pragma unroll
        for (int p = 0; p < 9; p++) {
            acc[p][0] = sb[0]; acc[p][1] = sb[1]; acc[p][2] = sb[2];
        }
#pragma unroll
        for (int ic = 0; ic < 3; ic++) {
            const float* chan = base + ic * 50176;
            float2 p2[7][4];
#pragma unroll
            for (int r = 0; r < 7; r++) {
                const float* rp = chan + r * 224;
                p2[r][0] = *(const float2*)(rp);
                p2[r][1] = *(const float2*)(rp + 2);
                p2[r][2] = *(const float2*)(rp + 4);
                p2[r][3] = *(const float2*)(rp + 6);
            }
#pragma unroll
            for (int ky = 0; ky < 3; ky++)
#pragma unroll
                for (int kx = 0; kx < 3; kx++) {
                    float w0 = sw[ic * 9 + ky * 3 + kx];
                    float w1 = sw[27 + ic * 9 + ky * 3 + kx];
                    float w2 = sw[54 + ic * 9 + ky * 3 + kx];
#pragma unroll
                    for (int cy = 0; cy < 3; cy++)
#pragma unroll
                        for (int cx = 0; cx < 3; cx++) {
                            int col = 2 * cx + kx;
                            float v = (col & 1) ? p2[2 * cy + ky][col >> 1].y
                                                : p2[2 * cy + ky][col >> 1].x;
                            acc[cy * 3 + cx][0] += v * w0;
                            acc[cy * 3 + cx][1] += v * w1;
                            acc[cy * 3 + cx][2] += v * w2;
                        }
                }
        }
#pragma unroll
        for (int oc = 0; oc < 3; oc++) {
            float m = acc[0][oc];
#pragma unroll
            for (int p = 1; p < 9; p++) m = fmaxf(m, acc[p][oc]);
            m = fmaxf(m, 0.0f);
            g_h1[(size_t)img * H1S + oc * 1369 + py * 37 + px] = m;
        }
    }

    // publish h1; per-image contribution count; last arriver runs conv2
    __threadfence();
    __syncthreads();
    if (t == 0) {
        int hi = (lo + 256 < TOTAL1) ? lo + 256 : TOTAL1;
        int i0 = lo / 1369;
        int i1 = (hi - 1) / 1369;
        int mask = 0;
        s_img[0] = i0; s_img[1] = i1;
        if (i0 == i1) {
            int c = hi - lo;
            if (atomicAdd(&g_imgcnt[i0], c) + c == 1369) mask |= 1;
        } else {
            int c0 = (i0 + 1) * 1369 - lo;
            int c1 = hi - i1 * 1369;
            if (atomicAdd(&g_imgcnt[i0], c0) + c0 == 1369) mask |= 1;
            if (atomicAdd(&g_imgcnt[i1], c1) + c1 == 1369) mask |= 2;
        }
        s_do = mask;
    }
    __syncthreads();
    int doMask = s_do;
    if (doMask == 0) return;
    __threadfence();                     // acquire other contributors' h1

#pragma unroll
    for (int k = 0; k < 2; k++) {
        if (doMask & (1 << k)) {
            const int img = s_img[k];
            for (int posn = t; posn < 324; posn += 256) {
                int pool = posn / 9, cp = posn - pool * 9;
                int py = pool / 6, px = pool - py * 6;
                int cy = 3 * py + cp / 3;
                int cx = 3 * px + cp % 3;
                const float* src = g_h1 + (size_t)img * H1S
                                        + (2 * cy) * 37 + 2 * cx;
                float v[27];
#pragma unroll
                for (int ic = 0; ic < 3; ic++)
#pragma unroll
                    for (int ky = 0; ky < 3; ky++)
#pragma unroll
                        for (int kx = 0; kx < 3; kx++)
                            v[ic * 9 + ky * 3 + kx] =
                                __ldg(src + ic * 1369 + ky * 37 + kx);
                float s = __ldg(c2b);
#pragma unroll
                for (int i = 0; i < 27; i++) s += v[i] * sw2[i];
                s_conv[pool][cp] = s;
            }
            __syncthreads();
            if (t < 36) {
                float m = s_conv[t][0];
#pragma unroll
                for (int p = 1; p < 9; p++) m = fmaxf(m, s_conv[t][p]);
                s_hs[t] = fmaxf(m, 0.0f);
            }
            __syncthreads();
            if (t < 6) {
                float s = __ldg(lb + t);
#pragma unroll
                for (int i = 0; i < 36; i++)
                    s += s_hs[i] * __ldg(lw + i * 6 + t);
                g_feat[img * 6 + t] = s;
            }
            __syncthreads();             // s_conv reuse if both images fire
        }
    }
}

// ---------------- Kernel 2: pure 16-block readout (sync-free) --------------
__global__ __launch_bounds__(256)
void readout_kernel(const float* __restrict__ pos,     // [16,5,4,6]
                    const float* __restrict__ attmap,  // [16,5,4,4]
                    const float* __restrict__ wfc_w, const float* __restrict__ wfc_b,
                    const float* __restrict__ fm_w,  const float* __restrict__ fm_b,
                    const float* __restrict__ lm_w,  const float* __restrict__ lm_b,
                    const float* __restrict__ fc1_w, const float* __restrict__ fc1_b,
                    const float* __restrict__ fc2_w, const float* __restrict__ fc2_b,
                    const float* __restrict__ fc3_w, const float* __restrict__ fc3_b,
                    float* __restrict__ out)           // [16,6]
{
    __shared__ float r_feat[20][6];
    __shared__ float r_ps[20][6];
    __shared__ float r_asrc[20];
    __shared__ float r_btgt[20];
    __shared__ float r_pm[20][6];
    __shared__ float r_inp[240];
    __shared__ float4 r_p4[8][30];
    __shared__ float4 r_p4b[4][15];
    __shared__ float r_r1[120];
    __shared__ float r_r2[60];

    const int n = blockIdx.x;
    const int t = threadIdx.x;

    // reset per-image counters for next graph replay (no dependency here)
    if (n == 0) {
        for (int i = t; i < NIMG; i += 256) g_imgcnt[i] = 0;
    }

    if (t < 120) {
        int fv = t / 6, d = t % 6;
        r_feat[fv][d] = g_feat[(n * 20 + fv) * 6 + d];
        r_ps[fv][d]   = pos[(n * 20 + fv) * 6 + d];
    }
    __syncthreads();

    if (t < 20) {
        float a = 0.0f, bb = 0.0f;
#pragma unroll
        for (int k = 0; k < 6; k++) {
            a  += r_feat[t][k] * __ldg(wfc_w + k)      + r_ps[t][k] * __ldg(wfc_w + 6 + k);
            bb += r_feat[t][k] * __ldg(wfc_w + 12 + k) + r_ps[t][k] * __ldg(wfc_w + 18 + k);
        }
        r_asrc[t] = a;
        r_btgt[t] = bb;
    }
    if (t >= 128 && t < 248) {
        int tt = t - 128;
        int fv = tt / 6, d = tt % 6;
        float s = __ldg(fm_b + d);
#pragma unroll
        for (int k = 0; k < 6; k++) s += r_ps[fv][k] * __ldg(fm_w + k * 6 + d);
        r_pm[fv][d] = s;
    }
    __syncthreads();

    if (t < 120) {
        int fv = t / 6, d = t % 6;
        int f = fv / 4, tv = fv % 4;
        float bias = __ldg(wfc_b);
        float agg = 0.0f;
#pragma unroll
        for (int s = 0; s < 4; s++) {
            float z  = r_asrc[f * 4 + s] + r_btgt[f * 4 + tv] + bias;
            float lk = 1.0f / (1.0f + expf(-z));
            float m  = lk + __ldg(attmap + ((n * 5 + f) * 4 + s) * 4 + tv);
            agg += m * r_pm[f * 4 + s][d];
        }
        if (f > 0) {
            float lm = __ldg(lm_b + d);
#pragma unroll
            for (int k = 0; k < 6; k++)
                lm += r_ps[(f - 1) * 4 + tv][k] * __ldg(lm_w + k * 6 + d);
            agg += lm;
        }
        r_inp[fv * 12 + d]     = r_feat[fv][d];
        r_inp[fv * 12 + 6 + d] = agg;
    }
    __syncthreads();

    // fc1 (240x120): 8 chunks x 30 quads; independent float4 chains
    if (t < 240) {
        int c = t / 30, q = t - (t / 30) * 30;
        const float4* wrow = (const float4*)fc1_w;
        float4 a = make_float4(0.f, 0.f, 0.f, 0.f);
#pragma unroll
        for (int i = 0; i < 30; i++) {
            float  x = r_inp[c * 30 + i];
            float4 w = __ldg(wrow + (c * 30 + i) * 30 + q);
            a.x += x * w.x; a.y += x * w.y; a.z += x * w.z; a.w += x * w.w;
        }
        r_p4[c][q] = a;
    }
    __syncthreads();
    if (t < 120) {
        int q = t >> 2, comp = t & 3;
        float s = __ldg(fc1_b + t);
#pragma unroll
        for (int c = 0; c < 8; c++) {
            float4 p = r_p4[c][q];
            s += (comp == 0) ? p.x : (comp == 1) ? p.y : (comp == 2) ? p.z : p.w;
        }
        r_r1[t] = fmaxf(s, 0.0f);
    }
    __syncthreads();

    // fc2 (120x60): 4 chunks x 15 quads
    if (t < 60) {
        int c = t / 15, q = t - (t / 15) * 15;
        const float4* wrow = (const float4*)fc2_w;
        float4 a = make_float4(0.f, 0.f, 0.f, 0.f);
#pragma unroll
        for (int i = 0; i < 30; i++) {
            float  x = r_r1[c * 30 + i];
            float4 w = __ldg(wrow + (c * 30 + i) * 15 + q);
            a.x += x * w.x; a.y += x * w.y; a.z += x * w.z; a.w += x * w.w;
        }
        r_p4b[c][q] = a;
    }
    __syncthreads();
    if (t < 60) {
        int q = t >> 2, comp = t & 3;
        float s = __ldg(fc2_b + t);
#pragma unroll
        for (int c = 0; c < 4; c++) {
            float4 p = r_p4b[c][q];
            s += (comp == 0) ? p.x : (comp == 1) ? p.y : (comp == 2) ? p.z : p.w;
        }
        r_r2[t] = fmaxf(s, 0.0f);
    }
    __syncthreads();

    if (t < 6) {
        float s = __ldg(fc3_b + t);
#pragma unroll
        for (int i = 0; i < 60; i++) s += r_r2[i] * __ldg(fc3_w + i * 6 + t);
        out[n * 6 + t] = s;
    }
}

// ---------------------------------------------------------------------------
extern "C" void kernel_launch(void* const* d_in, const int* in_sizes, int n_in,
                              void* d_out, int out_size)
{
    const float* nodes   = (const float*)d_in[0];
    const float* pos     = (const float*)d_in[1];
    const float* attmap  = (const float*)d_in[2];
    const float* conv1_w = (const float*)d_in[4];
    const float* conv1_b = (const float*)d_in[5];
    const float* conv2_w = (const float*)d_in[6];
    const float* conv2_b = (const float*)d_in[7];
    const float* lin_w   = (const float*)d_in[8];
    const float* lin_b   = (const float*)d_in[9];
    const float* wfc_w   = (const float*)d_in[10];
    const float* wfc_b   = (const float*)d_in[11];
    const float* fm_w    = (const float*)d_in[12];
    const float* fm_b    = (const float*)d_in[13];
    const float* lm_w    = (const float*)d_in[14];
    const float* lm_b    = (const float*)d_in[15];
    const float* fc1_w   = (const float*)d_in[16];
    const float* fc1_b   = (const float*)d_in[17];
    const float* fc2_w   = (const float*)d_in[18];
    const float* fc2_b   = (const float*)d_in[19];
    const float* fc3_w   = (const float*)d_in[20];
    const float* fc3_b   = (const float*)d_in[21];
    float* out = (float*)d_out;

    conv_fused_kernel<<<NBLK1, 256>>>(nodes, conv1_w, conv1_b,
                                      conv2_w, conv2_b, lin_w, lin_b);
    readout_kernel<<<16, 256>>>(pos, attmap, wfc_w, wfc_b, fm_w, fm_b,
                                lm_w, lm_b, fc1_w, fc1_b, fc2_w, fc2_b,
                                fc3_w, fc3_b, out);
}